// round 4
// baseline (speedup 1.0000x reference)
#include <cuda_runtime.h>
#include <math.h>
#include <stdint.h>

#define D_MODEL 512
#define NHEAD   8
#define D_HEAD  64
#define BATCH   2
#define LQ      2048
#define LK      4096

// Scratch (static device globals — allocation-free)
__device__ float g_Qp [BATCH * LQ * D_MODEL];   // 8 MB
__device__ float g_Kp [BATCH * LK * D_MODEL];   // 16 MB
__device__ float g_Vp [BATCH * LK * D_MODEL];   // 16 MB
__device__ float g_Att[BATCH * LQ * D_MODEL];   // 8 MB

// ---------------------------------------------------------------------------
// tf32 helpers
// ---------------------------------------------------------------------------
__device__ __forceinline__ uint32_t f2tf32(float f) {
    uint32_t r;
    asm("cvt.rna.tf32.f32 %0, %1;" : "=r"(r) : "f"(f));
    return r;
}
__device__ __forceinline__ float f2tf32f(float f) {
    return __uint_as_float(f2tf32(f));
}

// D += A(16x8,row) * B(8x8,col), tf32 in, fp32 acc
__device__ __forceinline__ void mma_tf32(float* d, const uint32_t* a,
                                         uint32_t b0, uint32_t b1) {
    asm volatile(
        "mma.sync.aligned.m16n8k8.row.col.f32.tf32.tf32.f32 "
        "{%0,%1,%2,%3},{%4,%5,%6,%7},{%8,%9},{%0,%1,%2,%3};"
        : "+f"(d[0]), "+f"(d[1]), "+f"(d[2]), "+f"(d[3])
        : "r"(a[0]), "r"(a[1]), "r"(a[2]), "r"(a[3]), "r"(b0), "r"(b1));
}

// ---------------------------------------------------------------------------
// GEMM: Y[M,512] = X[M,512] @ W[512,512]^T + bias (W row-major [out,in]).
// Tensor-core tf32. CTA tile 128x64, BK=32, 256 threads = 8 warps (4x2).
// Smem pad 36 (stride mod 32 == 4) => fragment LDS is conflict-free.
// ---------------------------------------------------------------------------
__global__ __launch_bounds__(256) void gemm_tc_kernel(
    const float* __restrict__ X, const float* __restrict__ W,
    const float* __restrict__ bias, float* __restrict__ Y)
{
    __shared__ float Xs[128][36];
    __shared__ float Ws[64][36];

    const int t      = threadIdx.x;
    const int lane   = t & 31;
    const int w      = t >> 5;
    const int warp_m = w >> 1;          // 0..3 -> 32 rows each
    const int warp_n = w & 1;           // 0..1 -> 32 cols each
    const int grp    = lane >> 2;       // 0..7
    const int tig    = lane & 3;        // 0..3
    const int m0     = blockIdx.y * 128;
    const int n0     = blockIdx.x * 64;

    float acc[2][4][4] = {};            // [mtile][ntile][frag]

    for (int k0 = 0; k0 < D_MODEL; k0 += 32) {
        // Fill Xs (128x32) and Ws (64x32), converting to tf32.
        #pragma unroll
        for (int rep = 0; rep < 4; rep++) {
            int idx = t + rep * 256;    // 0..1023
            int r = idx >> 3, c = idx & 7;
            float4 v = *(const float4*)(X + (size_t)(m0 + r) * D_MODEL + k0 + 4 * c);
            float4 o;
            o.x = f2tf32f(v.x); o.y = f2tf32f(v.y);
            o.z = f2tf32f(v.z); o.w = f2tf32f(v.w);
            *(float4*)&Xs[r][4 * c] = o;
        }
        #pragma unroll
        for (int rep = 0; rep < 2; rep++) {
            int idx = t + rep * 256;    // 0..511
            int r = idx >> 3, c = idx & 7;
            float4 v = *(const float4*)(W + (size_t)(n0 + r) * D_MODEL + k0 + 4 * c);
            float4 o;
            o.x = f2tf32f(v.x); o.y = f2tf32f(v.y);
            o.z = f2tf32f(v.z); o.w = f2tf32f(v.w);
            *(float4*)&Ws[r][4 * c] = o;
        }
        __syncthreads();

        #pragma unroll
        for (int ks = 0; ks < 4; ks++) {
            const int kk = ks * 8;
            uint32_t af[2][4];
            #pragma unroll
            for (int mt = 0; mt < 2; mt++) {
                int r = warp_m * 32 + mt * 16 + grp;
                af[mt][0] = __float_as_uint(Xs[r][kk + tig]);
                af[mt][1] = __float_as_uint(Xs[r + 8][kk + tig]);
                af[mt][2] = __float_as_uint(Xs[r][kk + tig + 4]);
                af[mt][3] = __float_as_uint(Xs[r + 8][kk + tig + 4]);
            }
            #pragma unroll
            for (int nt = 0; nt < 4; nt++) {
                int n = warp_n * 32 + nt * 8 + grp;
                uint32_t b0 = __float_as_uint(Ws[n][kk + tig]);
                uint32_t b1 = __float_as_uint(Ws[n][kk + tig + 4]);
                #pragma unroll
                for (int mt = 0; mt < 2; mt++)
                    mma_tf32(acc[mt][nt], af[mt], b0, b1);
            }
        }
        __syncthreads();
    }

    // Epilogue: + bias, write fp32
    #pragma unroll
    for (int mt = 0; mt < 2; mt++) {
        int r = m0 + warp_m * 32 + mt * 16 + grp;
        #pragma unroll
        for (int nt = 0; nt < 4; nt++) {
            int c = n0 + warp_n * 32 + nt * 8 + tig * 2;
            float b0 = bias[c], b1 = bias[c + 1];
            Y[(size_t)r * D_MODEL + c]           = acc[mt][nt][0] + b0;
            Y[(size_t)r * D_MODEL + c + 1]       = acc[mt][nt][1] + b1;
            Y[(size_t)(r + 8) * D_MODEL + c]     = acc[mt][nt][2] + b0;
            Y[(size_t)(r + 8) * D_MODEL + c + 1] = acc[mt][nt][3] + b1;
        }
    }
}

// ---------------------------------------------------------------------------
// Flash attention (tensor core). CTA = (b, h, 64-q-row tile). 256 thr, 8 warps.
// Warp tile: 16 q-rows (warp_m=w>>1) x 32 cols (warp_n=w&1).
// Q fragments in registers; K row-major and V transposed in smem (both are
// the `col` B operand). Parallel online softmax: 4 threads per row.
// ---------------------------------------------------------------------------
struct AttnSmem {
    float Ks[64][68];   // [kpos][d]   (tf32 bits)
    float Vt[64][68];   // [d][kpos]   (tf32 bits)
    float Ss[64][68];   // scores, then probabilities (tf32 bits)
    float gb[64];
    float mrow[64];
    float lrow[64];
    float cfac[64];
};
extern __shared__ unsigned char attn_smem_raw[];

__global__ __launch_bounds__(256) void attn_tc_kernel(
    const float* __restrict__ key_gate, const int* __restrict__ key_mask)
{
    AttnSmem& s = *reinterpret_cast<AttnSmem*>(attn_smem_raw);

    const int t      = threadIdx.x;
    const int lane   = t & 31;
    const int w      = t >> 5;
    const int warp_m = w >> 1;          // 0..3
    const int warp_n = w & 1;           // 0..1
    const int grp    = lane >> 2;
    const int tig    = lane & 3;
    const int q0     = blockIdx.x * 64;
    const int h      = blockIdx.y;
    const int b      = blockIdx.z;

    // --- Q fragments in registers (rows warp_m*16 .. +15, k = 0..63) ---
    const float* Qb = g_Qp + ((size_t)b * LQ + q0) * D_MODEL + h * D_HEAD;
    uint32_t qf[8][4];
    {
        const int r0 = warp_m * 16 + grp;
        #pragma unroll
        for (int ks = 0; ks < 8; ks++) {
            int kb = ks * 8;
            qf[ks][0] = f2tf32(Qb[(size_t)r0 * D_MODEL + kb + tig]);
            qf[ks][1] = f2tf32(Qb[(size_t)(r0 + 8) * D_MODEL + kb + tig]);
            qf[ks][2] = f2tf32(Qb[(size_t)r0 * D_MODEL + kb + tig + 4]);
            qf[ks][3] = f2tf32(Qb[(size_t)(r0 + 8) * D_MODEL + kb + tig + 4]);
        }
    }
    if (t < 64) { s.mrow[t] = -1e30f; s.lrow[t] = 0.0f; }

    float oacc[4][4] = {};
    const float scale = 0.125f;   // 1/sqrt(64)
    const int row  = t >> 2;      // softmax mapping: 4 threads / row
    const int part = t & 3;

    __syncthreads();

    for (int kt = 0; kt < LK / 64; kt++) {
        const int k0 = kt * 64;
        const float* Kb = g_Kp + ((size_t)b * LK + k0) * D_MODEL + h * D_HEAD;
        const float* Vb = g_Vp + ((size_t)b * LK + k0) * D_MODEL + h * D_HEAD;

        // Load K (row-major) and V (transposed), converting to tf32.
        #pragma unroll
        for (int rep = 0; rep < 4; rep++) {
            int idx = t + rep * 256;    // 0..1023
            int r = idx >> 4, c = idx & 15;
            float4 kv = *(const float4*)(Kb + (size_t)r * D_MODEL + 4 * c);
            float4 o;
            o.x = f2tf32f(kv.x); o.y = f2tf32f(kv.y);
            o.z = f2tf32f(kv.z); o.w = f2tf32f(kv.w);
            *(float4*)&s.Ks[r][4 * c] = o;
            float4 vv = *(const float4*)(Vb + (size_t)r * D_MODEL + 4 * c);
            s.Vt[4 * c + 0][r] = f2tf32f(vv.x);
            s.Vt[4 * c + 1][r] = f2tf32f(vv.y);
            s.Vt[4 * c + 2][r] = f2tf32f(vv.z);
            s.Vt[4 * c + 3][r] = f2tf32f(vv.w);
        }
        if (t < 64) {
            int k = k0 + t;
            float g = key_gate[(size_t)b * LK + k];
            s.gb[t] = (key_mask[(size_t)b * LK + k] == 0)
                          ? -1e30f : logf(fmaxf(g, 1e-6f));
        }
        __syncthreads();

        // ---- S = Q @ K^T (scaled) ----
        {
            float sacc[4][4] = {};
            #pragma unroll
            for (int ks = 0; ks < 8; ks++) {
                const int kk = ks * 8;
                #pragma unroll
                for (int nt = 0; nt < 4; nt++) {
                    int n = warp_n * 32 + nt * 8 + grp;
                    uint32_t b0 = __float_as_uint(s.Ks[n][kk + tig]);
                    uint32_t b1 = __float_as_uint(s.Ks[n][kk + tig + 4]);
                    mma_tf32(sacc[nt], qf[ks], b0, b1);
                }
            }
            const int r = warp_m * 16 + grp;
            #pragma unroll
            for (int nt = 0; nt < 4; nt++) {
                int c = warp_n * 32 + nt * 8 + tig * 2;
                s.Ss[r][c]         = sacc[nt][0] * scale;
                s.Ss[r][c + 1]     = sacc[nt][1] * scale;
                s.Ss[r + 8][c]     = sacc[nt][2] * scale;
                s.Ss[r + 8][c + 1] = sacc[nt][3] * scale;
            }
        }
        __syncthreads();

        // ---- online softmax: 4 threads per row, 16 cols each ----
        {
            float v[16];
            float mloc = -1e30f;
            #pragma unroll
            for (int i = 0; i < 4; i++) {
                float4 sv = *(float4*)&s.Ss[row][part * 16 + 4 * i];
                float4 gv = *(float4*)&s.gb[part * 16 + 4 * i];
                v[4*i+0] = sv.x + gv.x; v[4*i+1] = sv.y + gv.y;
                v[4*i+2] = sv.z + gv.z; v[4*i+3] = sv.w + gv.w;
                mloc = fmaxf(mloc, fmaxf(fmaxf(v[4*i], v[4*i+1]),
                                         fmaxf(v[4*i+2], v[4*i+3])));
            }
            mloc = fmaxf(mloc, __shfl_xor_sync(0xffffffff, mloc, 1));
            mloc = fmaxf(mloc, __shfl_xor_sync(0xffffffff, mloc, 2));
            float m_old = s.mrow[row];
            float m_new = fmaxf(m_old, mloc);

            float sum = 0.0f;
            #pragma unroll
            for (int i = 0; i < 4; i++) {
                float4 pv;
                float p0 = __expf(v[4*i+0] - m_new);
                float p1 = __expf(v[4*i+1] - m_new);
                float p2 = __expf(v[4*i+2] - m_new);
                float p3 = __expf(v[4*i+3] - m_new);
                sum += (p0 + p1) + (p2 + p3);
                pv.x = f2tf32f(p0); pv.y = f2tf32f(p1);
                pv.z = f2tf32f(p2); pv.w = f2tf32f(p3);
                *(float4*)&s.Ss[row][part * 16 + 4 * i] = pv;
            }
            sum += __shfl_xor_sync(0xffffffff, sum, 1);
            sum += __shfl_xor_sync(0xffffffff, sum, 2);
            if (part == 0) {
                float cf = __expf(m_old - m_new);
                s.cfac[row] = cf;
                s.lrow[row] = s.lrow[row] * cf + sum;
                s.mrow[row] = m_new;
            }
        }
        __syncthreads();

        // ---- O = O*cfac + P @ V ----
        {
            const int r = warp_m * 16 + grp;
            float cf0 = s.cfac[r], cf1 = s.cfac[r + 8];
            #pragma unroll
            for (int nt = 0; nt < 4; nt++) {
                oacc[nt][0] *= cf0; oacc[nt][1] *= cf0;
                oacc[nt][2] *= cf1; oacc[nt][3] *= cf1;
            }
            #pragma unroll
            for (int ks = 0; ks < 8; ks++) {
                const int kk = ks * 8;
                uint32_t af[4];
                af[0] = __float_as_uint(s.Ss[r][kk + tig]);
                af[1] = __float_as_uint(s.Ss[r + 8][kk + tig]);
                af[2] = __float_as_uint(s.Ss[r][kk + tig + 4]);
                af[3] = __float_as_uint(s.Ss[r + 8][kk + tig + 4]);
                #pragma unroll
                for (int nt = 0; nt < 4; nt++) {
                    int n = warp_n * 32 + nt * 8 + grp;
                    uint32_t b0 = __float_as_uint(s.Vt[n][kk + tig]);
                    uint32_t b1 = __float_as_uint(s.Vt[n][kk + tig + 4]);
                    mma_tf32(oacc[nt], af, b0, b1);
                }
            }
        }
        __syncthreads();
    }

    // ---- normalize + write ----
    {
        const int r = warp_m * 16 + grp;
        float l0 = 1.0f / s.lrow[r], l1 = 1.0f / s.lrow[r + 8];
        float* Ob = g_Att + ((size_t)b * LQ + q0) * D_MODEL + h * D_HEAD;
        #pragma unroll
        for (int nt = 0; nt < 4; nt++) {
            int c = warp_n * 32 + nt * 8 + tig * 2;
            Ob[(size_t)r * D_MODEL + c]           = oacc[nt][0] * l0;
            Ob[(size_t)r * D_MODEL + c + 1]       = oacc[nt][1] * l0;
            Ob[(size_t)(r + 8) * D_MODEL + c]     = oacc[nt][2] * l1;
            Ob[(size_t)(r + 8) * D_MODEL + c + 1] = oacc[nt][3] * l1;
        }
    }
}

// ---------------------------------------------------------------------------
// kernel_launch
// inputs: 0=q 1=kv 2=key_gate 3=key_mask 4=Wq 5=bq 6=Wk 7=bk 8=Wv 9=bv 10=Wo 11=bo
// ---------------------------------------------------------------------------
extern "C" void kernel_launch(void* const* d_in, const int* in_sizes, int n_in,
                              void* d_out, int out_size)
{
    (void)in_sizes; (void)n_in; (void)out_size;

    const float* q        = (const float*)d_in[0];
    const float* kv       = (const float*)d_in[1];
    const float* key_gate = (const float*)d_in[2];
    const int*   key_mask = (const int*)  d_in[3];
    const float* Wq = (const float*)d_in[4];
    const float* bq = (const float*)d_in[5];
    const float* Wk = (const float*)d_in[6];
    const float* bk = (const float*)d_in[7];
    const float* Wv = (const float*)d_in[8];
    const float* bv = (const float*)d_in[9];
    const float* Wo = (const float*)d_in[10];
    const float* bo = (const float*)d_in[11];
    float* out = (float*)d_out;

    float *pQp, *pKp, *pVp, *pAtt;
    cudaGetSymbolAddress((void**)&pQp,  g_Qp);
    cudaGetSymbolAddress((void**)&pKp,  g_Kp);
    cudaGetSymbolAddress((void**)&pVp,  g_Vp);
    cudaGetSymbolAddress((void**)&pAtt, g_Att);

    cudaFuncSetAttribute(attn_tc_kernel,
                         cudaFuncAttributeMaxDynamicSharedMemorySize,
                         (int)sizeof(AttnSmem));

    dim3 blk(256);
    // projections
    gemm_tc_kernel<<<dim3(8, (BATCH * LQ) / 128), blk>>>(q,  Wq, bq, pQp);
    gemm_tc_kernel<<<dim3(8, (BATCH * LK) / 128), blk>>>(kv, Wk, bk, pKp);
    gemm_tc_kernel<<<dim3(8, (BATCH * LK) / 128), blk>>>(kv, Wv, bv, pVp);
    // attention
    attn_tc_kernel<<<dim3(LQ / 64, NHEAD, BATCH), blk, sizeof(AttnSmem)>>>(
        key_gate, key_mask);
    // output projection
    gemm_tc_kernel<<<dim3(8, (BATCH * LQ) / 128), blk>>>(pAtt, Wo, bo, out);
}

// round 6
// speedup vs baseline: 1.0036x; 1.0036x over previous
#include <cuda_runtime.h>
#include <math.h>
#include <stdint.h>

#define D_MODEL 512
#define NHEAD   8
#define D_HEAD  64
#define BATCH   2
#define LQ      2048
#define LK      4096

// Scratch (static device globals — allocation-free)
__device__ float g_Qp [BATCH * LQ * D_MODEL];   // 8 MB
__device__ float g_Kp [BATCH * LK * D_MODEL];   // 16 MB
__device__ float g_Vp [BATCH * LK * D_MODEL];   // 16 MB
__device__ float g_Att[BATCH * LQ * D_MODEL];   // 8 MB

// ---------------------------------------------------------------------------
// tf32 helpers
// ---------------------------------------------------------------------------
__device__ __forceinline__ uint32_t f2tf32(float f) {
    uint32_t r;
    asm("cvt.rna.tf32.f32 %0, %1;" : "=r"(r) : "f"(f));
    return r;
}
__device__ __forceinline__ float f2tf32f(float f) {
    return __uint_as_float(f2tf32(f));
}

// D += A(16x8,row) * B(8x8,col), tf32 in, fp32 acc
__device__ __forceinline__ void mma_tf32(float* d, const uint32_t* a,
                                         uint32_t b0, uint32_t b1) {
    asm volatile(
        "mma.sync.aligned.m16n8k8.row.col.f32.tf32.tf32.f32 "
        "{%0,%1,%2,%3},{%4,%5,%6,%7},{%8,%9},{%0,%1,%2,%3};"
        : "+f"(d[0]), "+f"(d[1]), "+f"(d[2]), "+f"(d[3])
        : "r"(a[0]), "r"(a[1]), "r"(a[2]), "r"(a[3]), "r"(b0), "r"(b1));
}

// ---------------------------------------------------------------------------
// GEMM: Y[M,512] = X[M,512] @ W[512,512]^T + bias (W row-major [out,in]).
// Tensor-core tf32. CTA tile 128x64, BK=32, 256 threads = 8 warps (4x2).
// Smem pad 36 (stride mod 32 == 4) => fragment LDS is conflict-free.
// ---------------------------------------------------------------------------
__global__ __launch_bounds__(256) void gemm_tc_kernel(
    const float* __restrict__ X, const float* __restrict__ W,
    const float* __restrict__ bias, float* __restrict__ Y)
{
    __shared__ float Xs[128][36];
    __shared__ float Ws[64][36];

    const int t      = threadIdx.x;
    const int lane   = t & 31;
    const int w      = t >> 5;
    const int warp_m = w >> 1;          // 0..3 -> 32 rows each
    const int warp_n = w & 1;           // 0..1 -> 32 cols each
    const int grp    = lane >> 2;       // 0..7
    const int tig    = lane & 3;        // 0..3
    const int m0     = blockIdx.y * 128;
    const int n0     = blockIdx.x * 64;

    float acc[2][4][4] = {};            // [mtile][ntile][frag]

    for (int k0 = 0; k0 < D_MODEL; k0 += 32) {
        // Fill Xs (128x32) and Ws (64x32), converting to tf32.
        #pragma unroll
        for (int rep = 0; rep < 4; rep++) {
            int idx = t + rep * 256;    // 0..1023
            int r = idx >> 3, c = idx & 7;
            float4 v = *(const float4*)(X + (size_t)(m0 + r) * D_MODEL + k0 + 4 * c);
            float4 o;
            o.x = f2tf32f(v.x); o.y = f2tf32f(v.y);
            o.z = f2tf32f(v.z); o.w = f2tf32f(v.w);
            *(float4*)&Xs[r][4 * c] = o;
        }
        #pragma unroll
        for (int rep = 0; rep < 2; rep++) {
            int idx = t + rep * 256;    // 0..511
            int r = idx >> 3, c = idx & 7;
            float4 v = *(const float4*)(W + (size_t)(n0 + r) * D_MODEL + k0 + 4 * c);
            float4 o;
            o.x = f2tf32f(v.x); o.y = f2tf32f(v.y);
            o.z = f2tf32f(v.z); o.w = f2tf32f(v.w);
            *(float4*)&Ws[r][4 * c] = o;
        }
        __syncthreads();

        #pragma unroll
        for (int ks = 0; ks < 4; ks++) {
            const int kk = ks * 8;
            uint32_t af[2][4];
            #pragma unroll
            for (int mt = 0; mt < 2; mt++) {
                int r = warp_m * 32 + mt * 16 + grp;
                af[mt][0] = __float_as_uint(Xs[r][kk + tig]);
                af[mt][1] = __float_as_uint(Xs[r + 8][kk + tig]);
                af[mt][2] = __float_as_uint(Xs[r][kk + tig + 4]);
                af[mt][3] = __float_as_uint(Xs[r + 8][kk + tig + 4]);
            }
            #pragma unroll
            for (int nt = 0; nt < 4; nt++) {
                int n = warp_n * 32 + nt * 8 + grp;
                uint32_t b0 = __float_as_uint(Ws[n][kk + tig]);
                uint32_t b1 = __float_as_uint(Ws[n][kk + tig + 4]);
                #pragma unroll
                for (int mt = 0; mt < 2; mt++)
                    mma_tf32(acc[mt][nt], af[mt], b0, b1);
            }
        }
        __syncthreads();
    }

    // Epilogue: + bias, write fp32
    #pragma unroll
    for (int mt = 0; mt < 2; mt++) {
        int r = m0 + warp_m * 32 + mt * 16 + grp;
        #pragma unroll
        for (int nt = 0; nt < 4; nt++) {
            int c = n0 + warp_n * 32 + nt * 8 + tig * 2;
            float b0 = bias[c], b1 = bias[c + 1];
            Y[(size_t)r * D_MODEL + c]           = acc[mt][nt][0] + b0;
            Y[(size_t)r * D_MODEL + c + 1]       = acc[mt][nt][1] + b1;
            Y[(size_t)(r + 8) * D_MODEL + c]     = acc[mt][nt][2] + b0;
            Y[(size_t)(r + 8) * D_MODEL + c + 1] = acc[mt][nt][3] + b1;
        }
    }
}

// ---------------------------------------------------------------------------
// Flash attention (tensor core). CTA = (b, h, 64-q-row tile). 256 thr, 8 warps.
// Warp tile: 16 q-rows (warp_m=w>>1) x 32 cols (warp_n=w&1).
// Q fragments in registers; K row-major and V transposed in smem (both are
// the `col` B operand). Parallel online softmax: 4 threads per row.
// ---------------------------------------------------------------------------
struct AttnSmem {
    float Ks[64][68];   // [kpos][d]   (tf32 bits)
    float Vt[64][68];   // [d][kpos]   (tf32 bits)
    float Ss[64][68];   // scores, then probabilities (tf32 bits)
    float gb[64];
    float mrow[64];
    float lrow[64];
    float cfac[64];
};
extern __shared__ unsigned char attn_smem_raw[];

__global__ __launch_bounds__(256) void attn_tc_kernel(
    const float* __restrict__ key_gate, const int* __restrict__ key_mask)
{
    AttnSmem& s = *reinterpret_cast<AttnSmem*>(attn_smem_raw);

    const int t      = threadIdx.x;
    const int lane   = t & 31;
    const int w      = t >> 5;
    const int warp_m = w >> 1;          // 0..3
    const int warp_n = w & 1;           // 0..1
    const int grp    = lane >> 2;
    const int tig    = lane & 3;
    const int q0     = blockIdx.x * 64;
    const int h      = blockIdx.y;
    const int b      = blockIdx.z;

    // --- Q fragments in registers (rows warp_m*16 .. +15, k = 0..63) ---
    const float* Qb = g_Qp + ((size_t)b * LQ + q0) * D_MODEL + h * D_HEAD;
    uint32_t qf[8][4];
    {
        const int r0 = warp_m * 16 + grp;
        #pragma unroll
        for (int ks = 0; ks < 8; ks++) {
            int kb = ks * 8;
            qf[ks][0] = f2tf32(Qb[(size_t)r0 * D_MODEL + kb + tig]);
            qf[ks][1] = f2tf32(Qb[(size_t)(r0 + 8) * D_MODEL + kb + tig]);
            qf[ks][2] = f2tf32(Qb[(size_t)r0 * D_MODEL + kb + tig + 4]);
            qf[ks][3] = f2tf32(Qb[(size_t)(r0 + 8) * D_MODEL + kb + tig + 4]);
        }
    }
    if (t < 64) { s.mrow[t] = -1e30f; s.lrow[t] = 0.0f; }

    float oacc[4][4] = {};
    const float scale = 0.125f;   // 1/sqrt(64)
    const int row  = t >> 2;      // softmax mapping: 4 threads / row
    const int part = t & 3;

    __syncthreads();

    for (int kt = 0; kt < LK / 64; kt++) {
        const int k0 = kt * 64;
        const float* Kb = g_Kp + ((size_t)b * LK + k0) * D_MODEL + h * D_HEAD;
        const float* Vb = g_Vp + ((size_t)b * LK + k0) * D_MODEL + h * D_HEAD;

        // Load K (row-major) and V (transposed), converting to tf32.
        #pragma unroll
        for (int rep = 0; rep < 4; rep++) {
            int idx = t + rep * 256;    // 0..1023
            int r = idx >> 4, c = idx & 15;
            float4 kv = *(const float4*)(Kb + (size_t)r * D_MODEL + 4 * c);
            float4 o;
            o.x = f2tf32f(kv.x); o.y = f2tf32f(kv.y);
            o.z = f2tf32f(kv.z); o.w = f2tf32f(kv.w);
            *(float4*)&s.Ks[r][4 * c] = o;
            float4 vv = *(const float4*)(Vb + (size_t)r * D_MODEL + 4 * c);
            s.Vt[4 * c + 0][r] = f2tf32f(vv.x);
            s.Vt[4 * c + 1][r] = f2tf32f(vv.y);
            s.Vt[4 * c + 2][r] = f2tf32f(vv.z);
            s.Vt[4 * c + 3][r] = f2tf32f(vv.w);
        }
        if (t < 64) {
            int k = k0 + t;
            float g = key_gate[(size_t)b * LK + k];
            s.gb[t] = (key_mask[(size_t)b * LK + k] == 0)
                          ? -1e30f : logf(fmaxf(g, 1e-6f));
        }
        __syncthreads();

        // ---- S = Q @ K^T (scaled) ----
        {
            float sacc[4][4] = {};
            #pragma unroll
            for (int ks = 0; ks < 8; ks++) {
                const int kk = ks * 8;
                #pragma unroll
                for (int nt = 0; nt < 4; nt++) {
                    int n = warp_n * 32 + nt * 8 + grp;
                    uint32_t b0 = __float_as_uint(s.Ks[n][kk + tig]);
                    uint32_t b1 = __float_as_uint(s.Ks[n][kk + tig + 4]);
                    mma_tf32(sacc[nt], qf[ks], b0, b1);
                }
            }
            const int r = warp_m * 16 + grp;
            #pragma unroll
            for (int nt = 0; nt < 4; nt++) {
                int c = warp_n * 32 + nt * 8 + tig * 2;
                s.Ss[r][c]         = sacc[nt][0] * scale;
                s.Ss[r][c + 1]     = sacc[nt][1] * scale;
                s.Ss[r + 8][c]     = sacc[nt][2] * scale;
                s.Ss[r + 8][c + 1] = sacc[nt][3] * scale;
            }
        }
        __syncthreads();

        // ---- online softmax: 4 threads per row, 16 cols each ----
        {
            float v[16];
            float mloc = -1e30f;
            #pragma unroll
            for (int i = 0; i < 4; i++) {
                float4 sv = *(float4*)&s.Ss[row][part * 16 + 4 * i];
                float4 gv = *(float4*)&s.gb[part * 16 + 4 * i];
                v[4*i+0] = sv.x + gv.x; v[4*i+1] = sv.y + gv.y;
                v[4*i+2] = sv.z + gv.z; v[4*i+3] = sv.w + gv.w;
                mloc = fmaxf(mloc, fmaxf(fmaxf(v[4*i], v[4*i+1]),
                                         fmaxf(v[4*i+2], v[4*i+3])));
            }
            mloc = fmaxf(mloc, __shfl_xor_sync(0xffffffff, mloc, 1));
            mloc = fmaxf(mloc, __shfl_xor_sync(0xffffffff, mloc, 2));
            float m_old = s.mrow[row];
            float m_new = fmaxf(m_old, mloc);

            float sum = 0.0f;
            #pragma unroll
            for (int i = 0; i < 4; i++) {
                float4 pv;
                float p0 = __expf(v[4*i+0] - m_new);
                float p1 = __expf(v[4*i+1] - m_new);
                float p2 = __expf(v[4*i+2] - m_new);
                float p3 = __expf(v[4*i+3] - m_new);
                sum += (p0 + p1) + (p2 + p3);
                pv.x = f2tf32f(p0); pv.y = f2tf32f(p1);
                pv.z = f2tf32f(p2); pv.w = f2tf32f(p3);
                *(float4*)&s.Ss[row][part * 16 + 4 * i] = pv;
            }
            sum += __shfl_xor_sync(0xffffffff, sum, 1);
            sum += __shfl_xor_sync(0xffffffff, sum, 2);
            if (part == 0) {
                float cf = __expf(m_old - m_new);
                s.cfac[row] = cf;
                s.lrow[row] = s.lrow[row] * cf + sum;
                s.mrow[row] = m_new;
            }
        }
        __syncthreads();

        // ---- O = O*cfac + P @ V ----
        {
            const int r = warp_m * 16 + grp;
            float cf0 = s.cfac[r], cf1 = s.cfac[r + 8];
            #pragma unroll
            for (int nt = 0; nt < 4; nt++) {
                oacc[nt][0] *= cf0; oacc[nt][1] *= cf0;
                oacc[nt][2] *= cf1; oacc[nt][3] *= cf1;
            }
            #pragma unroll
            for (int ks = 0; ks < 8; ks++) {
                const int kk = ks * 8;
                uint32_t af[4];
                af[0] = __float_as_uint(s.Ss[r][kk + tig]);
                af[1] = __float_as_uint(s.Ss[r + 8][kk + tig]);
                af[2] = __float_as_uint(s.Ss[r][kk + tig + 4]);
                af[3] = __float_as_uint(s.Ss[r + 8][kk + tig + 4]);
                #pragma unroll
                for (int nt = 0; nt < 4; nt++) {
                    int n = warp_n * 32 + nt * 8 + grp;
                    uint32_t b0 = __float_as_uint(s.Vt[n][kk + tig]);
                    uint32_t b1 = __float_as_uint(s.Vt[n][kk + tig + 4]);
                    mma_tf32(oacc[nt], af, b0, b1);
                }
            }
        }
        __syncthreads();
    }

    // ---- normalize + write ----
    {
        const int r = warp_m * 16 + grp;
        float l0 = 1.0f / s.lrow[r], l1 = 1.0f / s.lrow[r + 8];
        float* Ob = g_Att + ((size_t)b * LQ + q0) * D_MODEL + h * D_HEAD;
        #pragma unroll
        for (int nt = 0; nt < 4; nt++) {
            int c = warp_n * 32 + nt * 8 + tig * 2;
            Ob[(size_t)r * D_MODEL + c]           = oacc[nt][0] * l0;
            Ob[(size_t)r * D_MODEL + c + 1]       = oacc[nt][1] * l0;
            Ob[(size_t)(r + 8) * D_MODEL + c]     = oacc[nt][2] * l1;
            Ob[(size_t)(r + 8) * D_MODEL + c + 1] = oacc[nt][3] * l1;
        }
    }
}

// ---------------------------------------------------------------------------
// kernel_launch
// inputs: 0=q 1=kv 2=key_gate 3=key_mask 4=Wq 5=bq 6=Wk 7=bk 8=Wv 9=bv 10=Wo 11=bo
// ---------------------------------------------------------------------------
extern "C" void kernel_launch(void* const* d_in, const int* in_sizes, int n_in,
                              void* d_out, int out_size)
{
    (void)in_sizes; (void)n_in; (void)out_size;

    const float* q        = (const float*)d_in[0];
    const float* kv       = (const float*)d_in[1];
    const float* key_gate = (const float*)d_in[2];
    const int*   key_mask = (const int*)  d_in[3];
    const float* Wq = (const float*)d_in[4];
    const float* bq = (const float*)d_in[5];
    const float* Wk = (const float*)d_in[6];
    const float* bk = (const float*)d_in[7];
    const float* Wv = (const float*)d_in[8];
    const float* bv = (const float*)d_in[9];
    const float* Wo = (const float*)d_in[10];
    const float* bo = (const float*)d_in[11];
    float* out = (float*)d_out;

    float *pQp, *pKp, *pVp, *pAtt;
    cudaGetSymbolAddress((void**)&pQp,  g_Qp);
    cudaGetSymbolAddress((void**)&pKp,  g_Kp);
    cudaGetSymbolAddress((void**)&pVp,  g_Vp);
    cudaGetSymbolAddress((void**)&pAtt, g_Att);

    cudaFuncSetAttribute(attn_tc_kernel,
                         cudaFuncAttributeMaxDynamicSharedMemorySize,
                         (int)sizeof(AttnSmem));

    dim3 blk(256);
    // projections
    gemm_tc_kernel<<<dim3(8, (BATCH * LQ) / 128), blk>>>(q,  Wq, bq, pQp);
    gemm_tc_kernel<<<dim3(8, (BATCH * LK) / 128), blk>>>(kv, Wk, bk, pKp);
    gemm_tc_kernel<<<dim3(8, (BATCH * LK) / 128), blk>>>(kv, Wv, bv, pVp);
    // attention
    attn_tc_kernel<<<dim3(LQ / 64, NHEAD, BATCH), blk, sizeof(AttnSmem)>>>(
        key_gate, key_mask);
    // output projection
    gemm_tc_kernel<<<dim3(8, (BATCH * LQ) / 128), blk>>>(pAtt, Wo, bo, out);
}

// round 7
// speedup vs baseline: 1.0038x; 1.0002x over previous
#include <cuda_runtime.h>
#include <math.h>
#include <stdint.h>

#define D_MODEL 512
#define NHEAD   8
#define D_HEAD  64
#define BATCH   2
#define LQ      2048
#define LK      4096

// Scratch (static device globals — allocation-free)
__device__ float g_Qp [BATCH * LQ * D_MODEL];   // 8 MB
__device__ float g_Kp [BATCH * LK * D_MODEL];   // 16 MB
__device__ float g_Vp [BATCH * LK * D_MODEL];   // 16 MB
__device__ float g_Att[BATCH * LQ * D_MODEL];   // 8 MB

// ---------------------------------------------------------------------------
// tf32 helpers
// ---------------------------------------------------------------------------
__device__ __forceinline__ uint32_t f2tf32(float f) {
    uint32_t r;
    asm("cvt.rna.tf32.f32 %0, %1;" : "=r"(r) : "f"(f));
    return r;
}
__device__ __forceinline__ float f2tf32f(float f) {
    return __uint_as_float(f2tf32(f));
}

// D += A(16x8,row) * B(8x8,col), tf32 in, fp32 acc
__device__ __forceinline__ void mma_tf32(float* d, const uint32_t* a,
                                         uint32_t b0, uint32_t b1) {
    asm volatile(
        "mma.sync.aligned.m16n8k8.row.col.f32.tf32.tf32.f32 "
        "{%0,%1,%2,%3},{%4,%5,%6,%7},{%8,%9},{%0,%1,%2,%3};"
        : "+f"(d[0]), "+f"(d[1]), "+f"(d[2]), "+f"(d[3])
        : "r"(a[0]), "r"(a[1]), "r"(a[2]), "r"(a[3]), "r"(b0), "r"(b1));
}

// ---------------------------------------------------------------------------
// GEMM: Y[M,512] = X[M,512] @ W[512,512]^T + bias (W row-major [out,in]).
// Tensor-core tf32. CTA tile 128x64, BK=32, 256 threads = 8 warps (4x2).
// Smem pad 36 (stride mod 32 == 4) => fragment LDS is conflict-free.
// ---------------------------------------------------------------------------
__global__ __launch_bounds__(256) void gemm_tc_kernel(
    const float* __restrict__ X, const float* __restrict__ W,
    const float* __restrict__ bias, float* __restrict__ Y)
{
    __shared__ float Xs[128][36];
    __shared__ float Ws[64][36];

    const int t      = threadIdx.x;
    const int lane   = t & 31;
    const int w      = t >> 5;
    const int warp_m = w >> 1;          // 0..3 -> 32 rows each
    const int warp_n = w & 1;           // 0..1 -> 32 cols each
    const int grp    = lane >> 2;       // 0..7
    const int tig    = lane & 3;        // 0..3
    const int m0     = blockIdx.y * 128;
    const int n0     = blockIdx.x * 64;

    float acc[2][4][4] = {};            // [mtile][ntile][frag]

    for (int k0 = 0; k0 < D_MODEL; k0 += 32) {
        // Fill Xs (128x32) and Ws (64x32), converting to tf32.
        #pragma unroll
        for (int rep = 0; rep < 4; rep++) {
            int idx = t + rep * 256;    // 0..1023
            int r = idx >> 3, c = idx & 7;
            float4 v = *(const float4*)(X + (size_t)(m0 + r) * D_MODEL + k0 + 4 * c);
            float4 o;
            o.x = f2tf32f(v.x); o.y = f2tf32f(v.y);
            o.z = f2tf32f(v.z); o.w = f2tf32f(v.w);
            *(float4*)&Xs[r][4 * c] = o;
        }
        #pragma unroll
        for (int rep = 0; rep < 2; rep++) {
            int idx = t + rep * 256;    // 0..511
            int r = idx >> 3, c = idx & 7;
            float4 v = *(const float4*)(W + (size_t)(n0 + r) * D_MODEL + k0 + 4 * c);
            float4 o;
            o.x = f2tf32f(v.x); o.y = f2tf32f(v.y);
            o.z = f2tf32f(v.z); o.w = f2tf32f(v.w);
            *(float4*)&Ws[r][4 * c] = o;
        }
        __syncthreads();

        #pragma unroll
        for (int ks = 0; ks < 4; ks++) {
            const int kk = ks * 8;
            uint32_t af[2][4];
            #pragma unroll
            for (int mt = 0; mt < 2; mt++) {
                int r = warp_m * 32 + mt * 16 + grp;
                af[mt][0] = __float_as_uint(Xs[r][kk + tig]);
                af[mt][1] = __float_as_uint(Xs[r + 8][kk + tig]);
                af[mt][2] = __float_as_uint(Xs[r][kk + tig + 4]);
                af[mt][3] = __float_as_uint(Xs[r + 8][kk + tig + 4]);
            }
            #pragma unroll
            for (int nt = 0; nt < 4; nt++) {
                int n = warp_n * 32 + nt * 8 + grp;
                uint32_t b0 = __float_as_uint(Ws[n][kk + tig]);
                uint32_t b1 = __float_as_uint(Ws[n][kk + tig + 4]);
                #pragma unroll
                for (int mt = 0; mt < 2; mt++)
                    mma_tf32(acc[mt][nt], af[mt], b0, b1);
            }
        }
        __syncthreads();
    }

    // Epilogue: + bias, write fp32
    #pragma unroll
    for (int mt = 0; mt < 2; mt++) {
        int r = m0 + warp_m * 32 + mt * 16 + grp;
        #pragma unroll
        for (int nt = 0; nt < 4; nt++) {
            int c = n0 + warp_n * 32 + nt * 8 + tig * 2;
            float b0 = bias[c], b1 = bias[c + 1];
            Y[(size_t)r * D_MODEL + c]           = acc[mt][nt][0] + b0;
            Y[(size_t)r * D_MODEL + c + 1]       = acc[mt][nt][1] + b1;
            Y[(size_t)(r + 8) * D_MODEL + c]     = acc[mt][nt][2] + b0;
            Y[(size_t)(r + 8) * D_MODEL + c + 1] = acc[mt][nt][3] + b1;
        }
    }
}

// ---------------------------------------------------------------------------
// Flash attention (tensor core). CTA = (b, h, 64-q-row tile). 256 thr, 8 warps.
// Warp tile: 16 q-rows (warp_m=w>>1) x 32 cols (warp_n=w&1).
// Q fragments in registers; K row-major and V transposed in smem (both are
// the `col` B operand). Parallel online softmax: 4 threads per row.
// ---------------------------------------------------------------------------
struct AttnSmem {
    float Ks[64][68];   // [kpos][d]   (tf32 bits)
    float Vt[64][68];   // [d][kpos]   (tf32 bits)
    float Ss[64][68];   // scores, then probabilities (tf32 bits)
    float gb[64];
    float mrow[64];
    float lrow[64];
    float cfac[64];
};
extern __shared__ unsigned char attn_smem_raw[];

__global__ __launch_bounds__(256) void attn_tc_kernel(
    const float* __restrict__ key_gate, const int* __restrict__ key_mask)
{
    AttnSmem& s = *reinterpret_cast<AttnSmem*>(attn_smem_raw);

    const int t      = threadIdx.x;
    const int lane   = t & 31;
    const int w      = t >> 5;
    const int warp_m = w >> 1;          // 0..3
    const int warp_n = w & 1;           // 0..1
    const int grp    = lane >> 2;
    const int tig    = lane & 3;
    const int q0     = blockIdx.x * 64;
    const int h      = blockIdx.y;
    const int b      = blockIdx.z;

    // --- Q fragments in registers (rows warp_m*16 .. +15, k = 0..63) ---
    const float* Qb = g_Qp + ((size_t)b * LQ + q0) * D_MODEL + h * D_HEAD;
    uint32_t qf[8][4];
    {
        const int r0 = warp_m * 16 + grp;
        #pragma unroll
        for (int ks = 0; ks < 8; ks++) {
            int kb = ks * 8;
            qf[ks][0] = f2tf32(Qb[(size_t)r0 * D_MODEL + kb + tig]);
            qf[ks][1] = f2tf32(Qb[(size_t)(r0 + 8) * D_MODEL + kb + tig]);
            qf[ks][2] = f2tf32(Qb[(size_t)r0 * D_MODEL + kb + tig + 4]);
            qf[ks][3] = f2tf32(Qb[(size_t)(r0 + 8) * D_MODEL + kb + tig + 4]);
        }
    }
    if (t < 64) { s.mrow[t] = -1e30f; s.lrow[t] = 0.0f; }

    float oacc[4][4] = {};
    const float scale = 0.125f;   // 1/sqrt(64)
    const int row  = t >> 2;      // softmax mapping: 4 threads / row
    const int part = t & 3;

    __syncthreads();

    for (int kt = 0; kt < LK / 64; kt++) {
        const int k0 = kt * 64;
        const float* Kb = g_Kp + ((size_t)b * LK + k0) * D_MODEL + h * D_HEAD;
        const float* Vb = g_Vp + ((size_t)b * LK + k0) * D_MODEL + h * D_HEAD;

        // Load K (row-major) and V (transposed), converting to tf32.
        #pragma unroll
        for (int rep = 0; rep < 4; rep++) {
            int idx = t + rep * 256;    // 0..1023
            int r = idx >> 4, c = idx & 15;
            float4 kv = *(const float4*)(Kb + (size_t)r * D_MODEL + 4 * c);
            float4 o;
            o.x = f2tf32f(kv.x); o.y = f2tf32f(kv.y);
            o.z = f2tf32f(kv.z); o.w = f2tf32f(kv.w);
            *(float4*)&s.Ks[r][4 * c] = o;
            float4 vv = *(const float4*)(Vb + (size_t)r * D_MODEL + 4 * c);
            s.Vt[4 * c + 0][r] = f2tf32f(vv.x);
            s.Vt[4 * c + 1][r] = f2tf32f(vv.y);
            s.Vt[4 * c + 2][r] = f2tf32f(vv.z);
            s.Vt[4 * c + 3][r] = f2tf32f(vv.w);
        }
        if (t < 64) {
            int k = k0 + t;
            float g = key_gate[(size_t)b * LK + k];
            s.gb[t] = (key_mask[(size_t)b * LK + k] == 0)
                          ? -1e30f : logf(fmaxf(g, 1e-6f));
        }
        __syncthreads();

        // ---- S = Q @ K^T (scaled) ----
        {
            float sacc[4][4] = {};
            #pragma unroll
            for (int ks = 0; ks < 8; ks++) {
                const int kk = ks * 8;
                #pragma unroll
                for (int nt = 0; nt < 4; nt++) {
                    int n = warp_n * 32 + nt * 8 + grp;
                    uint32_t b0 = __float_as_uint(s.Ks[n][kk + tig]);
                    uint32_t b1 = __float_as_uint(s.Ks[n][kk + tig + 4]);
                    mma_tf32(sacc[nt], qf[ks], b0, b1);
                }
            }
            const int r = warp_m * 16 + grp;
            #pragma unroll
            for (int nt = 0; nt < 4; nt++) {
                int c = warp_n * 32 + nt * 8 + tig * 2;
                s.Ss[r][c]         = sacc[nt][0] * scale;
                s.Ss[r][c + 1]     = sacc[nt][1] * scale;
                s.Ss[r + 8][c]     = sacc[nt][2] * scale;
                s.Ss[r + 8][c + 1] = sacc[nt][3] * scale;
            }
        }
        __syncthreads();

        // ---- online softmax: 4 threads per row, 16 cols each ----
        {
            float v[16];
            float mloc = -1e30f;
            #pragma unroll
            for (int i = 0; i < 4; i++) {
                float4 sv = *(float4*)&s.Ss[row][part * 16 + 4 * i];
                float4 gv = *(float4*)&s.gb[part * 16 + 4 * i];
                v[4*i+0] = sv.x + gv.x; v[4*i+1] = sv.y + gv.y;
                v[4*i+2] = sv.z + gv.z; v[4*i+3] = sv.w + gv.w;
                mloc = fmaxf(mloc, fmaxf(fmaxf(v[4*i], v[4*i+1]),
                                         fmaxf(v[4*i+2], v[4*i+3])));
            }
            mloc = fmaxf(mloc, __shfl_xor_sync(0xffffffff, mloc, 1));
            mloc = fmaxf(mloc, __shfl_xor_sync(0xffffffff, mloc, 2));
            float m_old = s.mrow[row];
            float m_new = fmaxf(m_old, mloc);

            float sum = 0.0f;
            #pragma unroll
            for (int i = 0; i < 4; i++) {
                float4 pv;
                float p0 = __expf(v[4*i+0] - m_new);
                float p1 = __expf(v[4*i+1] - m_new);
                float p2 = __expf(v[4*i+2] - m_new);
                float p3 = __expf(v[4*i+3] - m_new);
                sum += (p0 + p1) + (p2 + p3);
                pv.x = f2tf32f(p0); pv.y = f2tf32f(p1);
                pv.z = f2tf32f(p2); pv.w = f2tf32f(p3);
                *(float4*)&s.Ss[row][part * 16 + 4 * i] = pv;
            }
            sum += __shfl_xor_sync(0xffffffff, sum, 1);
            sum += __shfl_xor_sync(0xffffffff, sum, 2);
            if (part == 0) {
                float cf = __expf(m_old - m_new);
                s.cfac[row] = cf;
                s.lrow[row] = s.lrow[row] * cf + sum;
                s.mrow[row] = m_new;
            }
        }
        __syncthreads();

        // ---- O = O*cfac + P @ V ----
        {
            const int r = warp_m * 16 + grp;
            float cf0 = s.cfac[r], cf1 = s.cfac[r + 8];
            #pragma unroll
            for (int nt = 0; nt < 4; nt++) {
                oacc[nt][0] *= cf0; oacc[nt][1] *= cf0;
                oacc[nt][2] *= cf1; oacc[nt][3] *= cf1;
            }
            #pragma unroll
            for (int ks = 0; ks < 8; ks++) {
                const int kk = ks * 8;
                uint32_t af[4];
                af[0] = __float_as_uint(s.Ss[r][kk + tig]);
                af[1] = __float_as_uint(s.Ss[r + 8][kk + tig]);
                af[2] = __float_as_uint(s.Ss[r][kk + tig + 4]);
                af[3] = __float_as_uint(s.Ss[r + 8][kk + tig + 4]);
                #pragma unroll
                for (int nt = 0; nt < 4; nt++) {
                    int n = warp_n * 32 + nt * 8 + grp;
                    uint32_t b0 = __float_as_uint(s.Vt[n][kk + tig]);
                    uint32_t b1 = __float_as_uint(s.Vt[n][kk + tig + 4]);
                    mma_tf32(oacc[nt], af, b0, b1);
                }
            }
        }
        __syncthreads();
    }

    // ---- normalize + write ----
    {
        const int r = warp_m * 16 + grp;
        float l0 = 1.0f / s.lrow[r], l1 = 1.0f / s.lrow[r + 8];
        float* Ob = g_Att + ((size_t)b * LQ + q0) * D_MODEL + h * D_HEAD;
        #pragma unroll
        for (int nt = 0; nt < 4; nt++) {
            int c = warp_n * 32 + nt * 8 + tig * 2;
            Ob[(size_t)r * D_MODEL + c]           = oacc[nt][0] * l0;
            Ob[(size_t)r * D_MODEL + c + 1]       = oacc[nt][1] * l0;
            Ob[(size_t)(r + 8) * D_MODEL + c]     = oacc[nt][2] * l1;
            Ob[(size_t)(r + 8) * D_MODEL + c + 1] = oacc[nt][3] * l1;
        }
    }
}

// ---------------------------------------------------------------------------
// kernel_launch
// inputs: 0=q 1=kv 2=key_gate 3=key_mask 4=Wq 5=bq 6=Wk 7=bk 8=Wv 9=bv 10=Wo 11=bo
// ---------------------------------------------------------------------------
extern "C" void kernel_launch(void* const* d_in, const int* in_sizes, int n_in,
                              void* d_out, int out_size)
{
    (void)in_sizes; (void)n_in; (void)out_size;

    const float* q        = (const float*)d_in[0];
    const float* kv       = (const float*)d_in[1];
    const float* key_gate = (const float*)d_in[2];
    const int*   key_mask = (const int*)  d_in[3];
    const float* Wq = (const float*)d_in[4];
    const float* bq = (const float*)d_in[5];
    const float* Wk = (const float*)d_in[6];
    const float* bk = (const float*)d_in[7];
    const float* Wv = (const float*)d_in[8];
    const float* bv = (const float*)d_in[9];
    const float* Wo = (const float*)d_in[10];
    const float* bo = (const float*)d_in[11];
    float* out = (float*)d_out;

    float *pQp, *pKp, *pVp, *pAtt;
    cudaGetSymbolAddress((void**)&pQp,  g_Qp);
    cudaGetSymbolAddress((void**)&pKp,  g_Kp);
    cudaGetSymbolAddress((void**)&pVp,  g_Vp);
    cudaGetSymbolAddress((void**)&pAtt, g_Att);

    cudaFuncSetAttribute(attn_tc_kernel,
                         cudaFuncAttributeMaxDynamicSharedMemorySize,
                         (int)sizeof(AttnSmem));

    dim3 blk(256);
    // projections
    gemm_tc_kernel<<<dim3(8, (BATCH * LQ) / 128), blk>>>(q,  Wq, bq, pQp);
    gemm_tc_kernel<<<dim3(8, (BATCH * LK) / 128), blk>>>(kv, Wk, bk, pKp);
    gemm_tc_kernel<<<dim3(8, (BATCH * LK) / 128), blk>>>(kv, Wv, bv, pVp);
    // attention
    attn_tc_kernel<<<dim3(LQ / 64, NHEAD, BATCH), blk, sizeof(AttnSmem)>>>(
        key_gate, key_mask);
    // output projection
    gemm_tc_kernel<<<dim3(8, (BATCH * LQ) / 128), blk>>>(pAtt, Wo, bo, out);
}

// round 9
// speedup vs baseline: 1.0044x; 1.0006x over previous
#include <cuda_runtime.h>
#include <math.h>
#include <stdint.h>

#define D_MODEL 512
#define NHEAD   8
#define D_HEAD  64
#define BATCH   2
#define LQ      2048
#define LK      4096

// Scratch (static device globals — allocation-free)
__device__ float g_Qp [BATCH * LQ * D_MODEL];   // 8 MB
__device__ float g_Kp [BATCH * LK * D_MODEL];   // 16 MB
__device__ float g_Vp [BATCH * LK * D_MODEL];   // 16 MB
__device__ float g_Att[BATCH * LQ * D_MODEL];   // 8 MB

// ---------------------------------------------------------------------------
// tf32 helpers
// ---------------------------------------------------------------------------
__device__ __forceinline__ uint32_t f2tf32(float f) {
    uint32_t r;
    asm("cvt.rna.tf32.f32 %0, %1;" : "=r"(r) : "f"(f));
    return r;
}
__device__ __forceinline__ float f2tf32f(float f) {
    return __uint_as_float(f2tf32(f));
}

// D += A(16x8,row) * B(8x8,col), tf32 in, fp32 acc
__device__ __forceinline__ void mma_tf32(float* d, const uint32_t* a,
                                         uint32_t b0, uint32_t b1) {
    asm volatile(
        "mma.sync.aligned.m16n8k8.row.col.f32.tf32.tf32.f32 "
        "{%0,%1,%2,%3},{%4,%5,%6,%7},{%8,%9},{%0,%1,%2,%3};"
        : "+f"(d[0]), "+f"(d[1]), "+f"(d[2]), "+f"(d[3])
        : "r"(a[0]), "r"(a[1]), "r"(a[2]), "r"(a[3]), "r"(b0), "r"(b1));
}

// ---------------------------------------------------------------------------
// GEMM: Y[M,512] = X[M,512] @ W[512,512]^T + bias (W row-major [out,in]).
// Tensor-core tf32. CTA tile 128x64, BK=32, 256 threads = 8 warps (4x2).
// Smem pad 36 (stride mod 32 == 4) => fragment LDS is conflict-free.
// ---------------------------------------------------------------------------
__global__ __launch_bounds__(256) void gemm_tc_kernel(
    const float* __restrict__ X, const float* __restrict__ W,
    const float* __restrict__ bias, float* __restrict__ Y)
{
    __shared__ float Xs[128][36];
    __shared__ float Ws[64][36];

    const int t      = threadIdx.x;
    const int lane   = t & 31;
    const int w      = t >> 5;
    const int warp_m = w >> 1;          // 0..3 -> 32 rows each
    const int warp_n = w & 1;           // 0..1 -> 32 cols each
    const int grp    = lane >> 2;       // 0..7
    const int tig    = lane & 3;        // 0..3
    const int m0     = blockIdx.y * 128;
    const int n0     = blockIdx.x * 64;

    float acc[2][4][4] = {};            // [mtile][ntile][frag]

    for (int k0 = 0; k0 < D_MODEL; k0 += 32) {
        // Fill Xs (128x32) and Ws (64x32), converting to tf32.
        #pragma unroll
        for (int rep = 0; rep < 4; rep++) {
            int idx = t + rep * 256;    // 0..1023
            int r = idx >> 3, c = idx & 7;
            float4 v = *(const float4*)(X + (size_t)(m0 + r) * D_MODEL + k0 + 4 * c);
            float4 o;
            o.x = f2tf32f(v.x); o.y = f2tf32f(v.y);
            o.z = f2tf32f(v.z); o.w = f2tf32f(v.w);
            *(float4*)&Xs[r][4 * c] = o;
        }
        #pragma unroll
        for (int rep = 0; rep < 2; rep++) {
            int idx = t + rep * 256;    // 0..511
            int r = idx >> 3, c = idx & 7;
            float4 v = *(const float4*)(W + (size_t)(n0 + r) * D_MODEL + k0 + 4 * c);
            float4 o;
            o.x = f2tf32f(v.x); o.y = f2tf32f(v.y);
            o.z = f2tf32f(v.z); o.w = f2tf32f(v.w);
            *(float4*)&Ws[r][4 * c] = o;
        }
        __syncthreads();

        #pragma unroll
        for (int ks = 0; ks < 4; ks++) {
            const int kk = ks * 8;
            uint32_t af[2][4];
            #pragma unroll
            for (int mt = 0; mt < 2; mt++) {
                int r = warp_m * 32 + mt * 16 + grp;
                af[mt][0] = __float_as_uint(Xs[r][kk + tig]);
                af[mt][1] = __float_as_uint(Xs[r + 8][kk + tig]);
                af[mt][2] = __float_as_uint(Xs[r][kk + tig + 4]);
                af[mt][3] = __float_as_uint(Xs[r + 8][kk + tig + 4]);
            }
            #pragma unroll
            for (int nt = 0; nt < 4; nt++) {
                int n = warp_n * 32 + nt * 8 + grp;
                uint32_t b0 = __float_as_uint(Ws[n][kk + tig]);
                uint32_t b1 = __float_as_uint(Ws[n][kk + tig + 4]);
                #pragma unroll
                for (int mt = 0; mt < 2; mt++)
                    mma_tf32(acc[mt][nt], af[mt], b0, b1);
            }
        }
        __syncthreads();
    }

    // Epilogue: + bias, write fp32
    #pragma unroll
    for (int mt = 0; mt < 2; mt++) {
        int r = m0 + warp_m * 32 + mt * 16 + grp;
        #pragma unroll
        for (int nt = 0; nt < 4; nt++) {
            int c = n0 + warp_n * 32 + nt * 8 + tig * 2;
            float b0 = bias[c], b1 = bias[c + 1];
            Y[(size_t)r * D_MODEL + c]           = acc[mt][nt][0] + b0;
            Y[(size_t)r * D_MODEL + c + 1]       = acc[mt][nt][1] + b1;
            Y[(size_t)(r + 8) * D_MODEL + c]     = acc[mt][nt][2] + b0;
            Y[(size_t)(r + 8) * D_MODEL + c + 1] = acc[mt][nt][3] + b1;
        }
    }
}

// ---------------------------------------------------------------------------
// Flash attention (tensor core). CTA = (b, h, 64-q-row tile). 256 thr, 8 warps.
// Warp tile: 16 q-rows (warp_m=w>>1) x 32 cols (warp_n=w&1).
// Q fragments in registers; K row-major and V transposed in smem (both are
// the `col` B operand). Parallel online softmax: 4 threads per row.
// ---------------------------------------------------------------------------
struct AttnSmem {
    float Ks[64][68];   // [kpos][d]   (tf32 bits)
    float Vt[64][68];   // [d][kpos]   (tf32 bits)
    float Ss[64][68];   // scores, then probabilities (tf32 bits)
    float gb[64];
    float mrow[64];
    float lrow[64];
    float cfac[64];
};
extern __shared__ unsigned char attn_smem_raw[];

__global__ __launch_bounds__(256) void attn_tc_kernel(
    const float* __restrict__ key_gate, const int* __restrict__ key_mask)
{
    AttnSmem& s = *reinterpret_cast<AttnSmem*>(attn_smem_raw);

    const int t      = threadIdx.x;
    const int lane   = t & 31;
    const int w      = t >> 5;
    const int warp_m = w >> 1;          // 0..3
    const int warp_n = w & 1;           // 0..1
    const int grp    = lane >> 2;
    const int tig    = lane & 3;
    const int q0     = blockIdx.x * 64;
    const int h      = blockIdx.y;
    const int b      = blockIdx.z;

    // --- Q fragments in registers (rows warp_m*16 .. +15, k = 0..63) ---
    const float* Qb = g_Qp + ((size_t)b * LQ + q0) * D_MODEL + h * D_HEAD;
    uint32_t qf[8][4];
    {
        const int r0 = warp_m * 16 + grp;
        #pragma unroll
        for (int ks = 0; ks < 8; ks++) {
            int kb = ks * 8;
            qf[ks][0] = f2tf32(Qb[(size_t)r0 * D_MODEL + kb + tig]);
            qf[ks][1] = f2tf32(Qb[(size_t)(r0 + 8) * D_MODEL + kb + tig]);
            qf[ks][2] = f2tf32(Qb[(size_t)r0 * D_MODEL + kb + tig + 4]);
            qf[ks][3] = f2tf32(Qb[(size_t)(r0 + 8) * D_MODEL + kb + tig + 4]);
        }
    }
    if (t < 64) { s.mrow[t] = -1e30f; s.lrow[t] = 0.0f; }

    float oacc[4][4] = {};
    const float scale = 0.125f;   // 1/sqrt(64)
    const int row  = t >> 2;      // softmax mapping: 4 threads / row
    const int part = t & 3;

    __syncthreads();

    for (int kt = 0; kt < LK / 64; kt++) {
        const int k0 = kt * 64;
        const float* Kb = g_Kp + ((size_t)b * LK + k0) * D_MODEL + h * D_HEAD;
        const float* Vb = g_Vp + ((size_t)b * LK + k0) * D_MODEL + h * D_HEAD;

        // Load K (row-major) and V (transposed), converting to tf32.
        #pragma unroll
        for (int rep = 0; rep < 4; rep++) {
            int idx = t + rep * 256;    // 0..1023
            int r = idx >> 4, c = idx & 15;
            float4 kv = *(const float4*)(Kb + (size_t)r * D_MODEL + 4 * c);
            float4 o;
            o.x = f2tf32f(kv.x); o.y = f2tf32f(kv.y);
            o.z = f2tf32f(kv.z); o.w = f2tf32f(kv.w);
            *(float4*)&s.Ks[r][4 * c] = o;
            float4 vv = *(const float4*)(Vb + (size_t)r * D_MODEL + 4 * c);
            s.Vt[4 * c + 0][r] = f2tf32f(vv.x);
            s.Vt[4 * c + 1][r] = f2tf32f(vv.y);
            s.Vt[4 * c + 2][r] = f2tf32f(vv.z);
            s.Vt[4 * c + 3][r] = f2tf32f(vv.w);
        }
        if (t < 64) {
            int k = k0 + t;
            float g = key_gate[(size_t)b * LK + k];
            s.gb[t] = (key_mask[(size_t)b * LK + k] == 0)
                          ? -1e30f : logf(fmaxf(g, 1e-6f));
        }
        __syncthreads();

        // ---- S = Q @ K^T (scaled) ----
        {
            float sacc[4][4] = {};
            #pragma unroll
            for (int ks = 0; ks < 8; ks++) {
                const int kk = ks * 8;
                #pragma unroll
                for (int nt = 0; nt < 4; nt++) {
                    int n = warp_n * 32 + nt * 8 + grp;
                    uint32_t b0 = __float_as_uint(s.Ks[n][kk + tig]);
                    uint32_t b1 = __float_as_uint(s.Ks[n][kk + tig + 4]);
                    mma_tf32(sacc[nt], qf[ks], b0, b1);
                }
            }
            const int r = warp_m * 16 + grp;
            #pragma unroll
            for (int nt = 0; nt < 4; nt++) {
                int c = warp_n * 32 + nt * 8 + tig * 2;
                s.Ss[r][c]         = sacc[nt][0] * scale;
                s.Ss[r][c + 1]     = sacc[nt][1] * scale;
                s.Ss[r + 8][c]     = sacc[nt][2] * scale;
                s.Ss[r + 8][c + 1] = sacc[nt][3] * scale;
            }
        }
        __syncthreads();

        // ---- online softmax: 4 threads per row, 16 cols each ----
        {
            float v[16];
            float mloc = -1e30f;
            #pragma unroll
            for (int i = 0; i < 4; i++) {
                float4 sv = *(float4*)&s.Ss[row][part * 16 + 4 * i];
                float4 gv = *(float4*)&s.gb[part * 16 + 4 * i];
                v[4*i+0] = sv.x + gv.x; v[4*i+1] = sv.y + gv.y;
                v[4*i+2] = sv.z + gv.z; v[4*i+3] = sv.w + gv.w;
                mloc = fmaxf(mloc, fmaxf(fmaxf(v[4*i], v[4*i+1]),
                                         fmaxf(v[4*i+2], v[4*i+3])));
            }
            mloc = fmaxf(mloc, __shfl_xor_sync(0xffffffff, mloc, 1));
            mloc = fmaxf(mloc, __shfl_xor_sync(0xffffffff, mloc, 2));
            float m_old = s.mrow[row];
            float m_new = fmaxf(m_old, mloc);

            float sum = 0.0f;
            #pragma unroll
            for (int i = 0; i < 4; i++) {
                float4 pv;
                float p0 = __expf(v[4*i+0] - m_new);
                float p1 = __expf(v[4*i+1] - m_new);
                float p2 = __expf(v[4*i+2] - m_new);
                float p3 = __expf(v[4*i+3] - m_new);
                sum += (p0 + p1) + (p2 + p3);
                pv.x = f2tf32f(p0); pv.y = f2tf32f(p1);
                pv.z = f2tf32f(p2); pv.w = f2tf32f(p3);
                *(float4*)&s.Ss[row][part * 16 + 4 * i] = pv;
            }
            sum += __shfl_xor_sync(0xffffffff, sum, 1);
            sum += __shfl_xor_sync(0xffffffff, sum, 2);
            if (part == 0) {
                float cf = __expf(m_old - m_new);
                s.cfac[row] = cf;
                s.lrow[row] = s.lrow[row] * cf + sum;
                s.mrow[row] = m_new;
            }
        }
        __syncthreads();

        // ---- O = O*cfac + P @ V ----
        {
            const int r = warp_m * 16 + grp;
            float cf0 = s.cfac[r], cf1 = s.cfac[r + 8];
            #pragma unroll
            for (int nt = 0; nt < 4; nt++) {
                oacc[nt][0] *= cf0; oacc[nt][1] *= cf0;
                oacc[nt][2] *= cf1; oacc[nt][3] *= cf1;
            }
            #pragma unroll
            for (int ks = 0; ks < 8; ks++) {
                const int kk = ks * 8;
                uint32_t af[4];
                af[0] = __float_as_uint(s.Ss[r][kk + tig]);
                af[1] = __float_as_uint(s.Ss[r + 8][kk + tig]);
                af[2] = __float_as_uint(s.Ss[r][kk + tig + 4]);
                af[3] = __float_as_uint(s.Ss[r + 8][kk + tig + 4]);
                #pragma unroll
                for (int nt = 0; nt < 4; nt++) {
                    int n = warp_n * 32 + nt * 8 + grp;
                    uint32_t b0 = __float_as_uint(s.Vt[n][kk + tig]);
                    uint32_t b1 = __float_as_uint(s.Vt[n][kk + tig + 4]);
                    mma_tf32(oacc[nt], af, b0, b1);
                }
            }
        }
        __syncthreads();
    }

    // ---- normalize + write ----
    {
        const int r = warp_m * 16 + grp;
        float l0 = 1.0f / s.lrow[r], l1 = 1.0f / s.lrow[r + 8];
        float* Ob = g_Att + ((size_t)b * LQ + q0) * D_MODEL + h * D_HEAD;
        #pragma unroll
        for (int nt = 0; nt < 4; nt++) {
            int c = warp_n * 32 + nt * 8 + tig * 2;
            Ob[(size_t)r * D_MODEL + c]           = oacc[nt][0] * l0;
            Ob[(size_t)r * D_MODEL + c + 1]       = oacc[nt][1] * l0;
            Ob[(size_t)(r + 8) * D_MODEL + c]     = oacc[nt][2] * l1;
            Ob[(size_t)(r + 8) * D_MODEL + c + 1] = oacc[nt][3] * l1;
        }
    }
}

// ---------------------------------------------------------------------------
// kernel_launch
// inputs: 0=q 1=kv 2=key_gate 3=key_mask 4=Wq 5=bq 6=Wk 7=bk 8=Wv 9=bv 10=Wo 11=bo
// ---------------------------------------------------------------------------
extern "C" void kernel_launch(void* const* d_in, const int* in_sizes, int n_in,
                              void* d_out, int out_size)
{
    (void)in_sizes; (void)n_in; (void)out_size;

    const float* q        = (const float*)d_in[0];
    const float* kv       = (const float*)d_in[1];
    const float* key_gate = (const float*)d_in[2];
    const int*   key_mask = (const int*)  d_in[3];
    const float* Wq = (const float*)d_in[4];
    const float* bq = (const float*)d_in[5];
    const float* Wk = (const float*)d_in[6];
    const float* bk = (const float*)d_in[7];
    const float* Wv = (const float*)d_in[8];
    const float* bv = (const float*)d_in[9];
    const float* Wo = (const float*)d_in[10];
    const float* bo = (const float*)d_in[11];
    float* out = (float*)d_out;

    float *pQp, *pKp, *pVp, *pAtt;
    cudaGetSymbolAddress((void**)&pQp,  g_Qp);
    cudaGetSymbolAddress((void**)&pKp,  g_Kp);
    cudaGetSymbolAddress((void**)&pVp,  g_Vp);
    cudaGetSymbolAddress((void**)&pAtt, g_Att);

    cudaFuncSetAttribute(attn_tc_kernel,
                         cudaFuncAttributeMaxDynamicSharedMemorySize,
                         (int)sizeof(AttnSmem));

    dim3 blk(256);
    // projections
    gemm_tc_kernel<<<dim3(8, (BATCH * LQ) / 128), blk>>>(q,  Wq, bq, pQp);
    gemm_tc_kernel<<<dim3(8, (BATCH * LK) / 128), blk>>>(kv, Wk, bk, pKp);
    gemm_tc_kernel<<<dim3(8, (BATCH * LK) / 128), blk>>>(kv, Wv, bv, pVp);
    // attention
    attn_tc_kernel<<<dim3(LQ / 64, NHEAD, BATCH), blk, sizeof(AttnSmem)>>>(
        key_gate, key_mask);
    // output projection
    gemm_tc_kernel<<<dim3(8, (BATCH * LQ) / 128), blk>>>(pAtt, Wo, bo, out);
}